// round 1
// baseline (speedup 1.0000x reference)
#include <cuda_runtime.h>

#define B_   1024
#define D_   1024
#define G_   4096
#define BAR_ 32
#define EPS_ 1e-5f

// ---------------- device scratch (no allocations allowed) ----------------
__device__ float g_sum[D_];
__device__ float g_sumsq[D_];
__device__ float g_zn[B_ * D_];
__device__ float g_x0[B_ * G_];            // x0_proj = zn @ W_ih0^T + b_ih0
__device__ float g_gates[B_ * G_];
__device__ float g_h0[B_ * D_];
__device__ float g_c0[B_ * D_];
__device__ float g_c1[B_ * D_];
__device__ float g_h1init[B_ * D_];
__device__ float g_hist[(size_t)BAR_ * B_ * D_];  // h1 per step, [t][b][d]

// ---------------- BatchNorm ----------------
__global__ void bn_reduce(const float* __restrict__ z) {
    int c = blockIdx.x;
    int tid = threadIdx.x;
    float s = 0.f, s2 = 0.f;
    for (int r = tid; r < B_; r += 256) {
        float v = z[(size_t)r * D_ + c];
        s += v; s2 += v * v;
    }
    __shared__ float sh[256], sh2[256];
    sh[tid] = s; sh2[tid] = s2;
    __syncthreads();
    for (int o = 128; o > 0; o >>= 1) {
        if (tid < o) { sh[tid] += sh[tid + o]; sh2[tid] += sh2[tid + o]; }
        __syncthreads();
    }
    if (tid == 0) { g_sum[c] = sh[0]; g_sumsq[c] = sh2[0]; }
}

__global__ void bn_apply(const float* __restrict__ z,
                         const float* __restrict__ gamma,
                         const float* __restrict__ beta) {
    int idx = blockIdx.x * 256 + threadIdx.x;
    int d = idx & (D_ - 1);
    float mean = g_sum[d] * (1.f / B_);
    float var  = g_sumsq[d] * (1.f / B_) - mean * mean;
    float v = (z[idx] - mean) * rsqrtf(var + EPS_) * gamma[d] + beta[d];
    g_zn[idx] = v;
    g_h0[idx] = v;
    g_c0[idx] = v;
    g_c1[idx] = v;
    g_h1init[idx] = v;
}

// ---------------- LSTM cell (elementwise) ----------------
__device__ __forceinline__ float sigf(float x) { return 1.f / (1.f + __expf(-x)); }

__global__ void lstm_cell(const float* __restrict__ gates,
                          float* __restrict__ c,
                          float* __restrict__ hout) {
    int idx = blockIdx.x * 256 + threadIdx.x;
    int b = idx >> 10;
    int d = idx & 1023;
    const float* gr = gates + (size_t)b * G_;
    float gi = gr[d];
    float gf = gr[D_ + d];
    float gg = gr[2 * D_ + d];
    float go = gr[3 * D_ + d];
    float cn = sigf(gf) * c[idx] + sigf(gi) * tanhf(gg);
    c[idx] = cn;
    hout[idx] = sigf(go) * tanhf(cn);
}

// ---------------- SGEMM (NT): C = [Cin] + bias1 + [bias2] + A1*B1^T + [A2*B2^T] ----------------
// A: MxK row-major, B: NxK row-major. 128x128 tile, BK=16, 256 threads, 8x8/thread.
__global__ void __launch_bounds__(256) sgemm_nt(
    const float* __restrict__ A1, const float* __restrict__ B1,
    const float* __restrict__ A2, const float* __restrict__ B2,
    const float* __restrict__ Cin,
    const float* __restrict__ bias1, const float* __restrict__ bias2,
    float* __restrict__ C, int M, int N, int K, int permute)
{
    __shared__ float As[16][128];
    __shared__ float Bs[16][128];

    const int tid = threadIdx.x;
    const int m0 = blockIdx.y * 128;
    const int n0 = blockIdx.x * 128;

    const int r0 = tid >> 2;          // 0..63
    const int r1 = r0 + 64;           // 64..127
    const int kk = (tid & 3) << 2;    // 0,4,8,12

    const int tx = tid & 15;
    const int ty = tid >> 4;
    const int mo = ty << 3;
    const int no = tx << 3;

    float acc[8][8];
#pragma unroll
    for (int i = 0; i < 8; i++)
#pragma unroll
        for (int j = 0; j < 8; j++) acc[i][j] = 0.f;

    const int nt1 = K >> 4;
    const int total = A2 ? (nt1 << 1) : nt1;

    for (int kt = 0; kt < total; kt++) {
        int ktl = kt;
        const float* A = A1;
        const float* Bm = B1;
        if (kt >= nt1) { ktl = kt - nt1; A = A2; Bm = B2; }
        const int k0 = ktl << 4;

        float4 a0 = *(const float4*)(A  + (size_t)(m0 + r0) * K + k0 + kk);
        float4 a1 = *(const float4*)(A  + (size_t)(m0 + r1) * K + k0 + kk);
        float4 b0 = *(const float4*)(Bm + (size_t)(n0 + r0) * K + k0 + kk);
        float4 b1 = *(const float4*)(Bm + (size_t)(n0 + r1) * K + k0 + kk);

        __syncthreads();
        As[kk + 0][r0] = a0.x; As[kk + 1][r0] = a0.y; As[kk + 2][r0] = a0.z; As[kk + 3][r0] = a0.w;
        As[kk + 0][r1] = a1.x; As[kk + 1][r1] = a1.y; As[kk + 2][r1] = a1.z; As[kk + 3][r1] = a1.w;
        Bs[kk + 0][r0] = b0.x; Bs[kk + 1][r0] = b0.y; Bs[kk + 2][r0] = b0.z; Bs[kk + 3][r0] = b0.w;
        Bs[kk + 0][r1] = b1.x; Bs[kk + 1][r1] = b1.y; Bs[kk + 2][r1] = b1.z; Bs[kk + 3][r1] = b1.w;
        __syncthreads();

#pragma unroll
        for (int k = 0; k < 16; k++) {
            float4 af0 = *(const float4*)&As[k][mo];
            float4 af1 = *(const float4*)&As[k][mo + 4];
            float4 bf0 = *(const float4*)&Bs[k][no];
            float4 bf1 = *(const float4*)&Bs[k][no + 4];
            float a[8] = {af0.x, af0.y, af0.z, af0.w, af1.x, af1.y, af1.z, af1.w};
            float b[8] = {bf0.x, bf0.y, bf0.z, bf0.w, bf1.x, bf1.y, bf1.z, bf1.w};
#pragma unroll
            for (int i = 0; i < 8; i++)
#pragma unroll
                for (int j = 0; j < 8; j++)
                    acc[i][j] = fmaf(a[i], b[j], acc[i][j]);
        }
    }

#pragma unroll
    for (int i = 0; i < 8; i++) {
        int m = m0 + mo + i;
#pragma unroll
        for (int j = 0; j < 8; j++) {
            int n = n0 + no + j;
            float v = acc[i][j];
            if (bias1) v += bias1[n];
            if (bias2) v += bias2[n];
            if (Cin)   v += Cin[(size_t)m * N + n];
            size_t o;
            if (permute) {
                int t = m >> 10;        // row = t*B + b with B=1024
                int bb = m & 1023;
                o = ((size_t)bb * BAR_ + t) * (size_t)D_ + n;
            } else {
                o = (size_t)m * N + n;
            }
            C[o] = v;
        }
    }
}

// ---------------- launcher ----------------
extern "C" void kernel_launch(void* const* d_in, const int* in_sizes, int n_in,
                              void* d_out, int out_size)
{
    const float* z     = (const float*)d_in[0];
    const float* gamma = (const float*)d_in[1];
    const float* beta  = (const float*)d_in[2];
    const float* W_ih0 = (const float*)d_in[3];
    const float* W_hh0 = (const float*)d_in[4];
    const float* b_ih0 = (const float*)d_in[5];
    const float* b_hh0 = (const float*)d_in[6];
    const float* W_ih1 = (const float*)d_in[7];
    const float* W_hh1 = (const float*)d_in[8];
    const float* b_ih1 = (const float*)d_in[9];
    const float* b_hh1 = (const float*)d_in[10];
    const float* W_lin = (const float*)d_in[11];
    const float* b_lin = (const float*)d_in[12];
    float* out = (float*)d_out;

    float *zn, *x0, *gates, *h0, *c0, *c1, *h1i, *hist;
    cudaGetSymbolAddress((void**)&zn,    g_zn);
    cudaGetSymbolAddress((void**)&x0,    g_x0);
    cudaGetSymbolAddress((void**)&gates, g_gates);
    cudaGetSymbolAddress((void**)&h0,    g_h0);
    cudaGetSymbolAddress((void**)&c0,    g_c0);
    cudaGetSymbolAddress((void**)&c1,    g_c1);
    cudaGetSymbolAddress((void**)&h1i,   g_h1init);
    cudaGetSymbolAddress((void**)&hist,  g_hist);

    bn_reduce<<<D_, 256>>>(z);
    bn_apply<<<(B_ * D_) / 256, 256>>>(z, gamma, beta);

    // x0_proj = zn @ W_ih0^T + b_ih0
    sgemm_nt<<<dim3(G_ / 128, B_ / 128), 256>>>(
        zn, W_ih0, nullptr, nullptr, nullptr, b_ih0, nullptr,
        x0, B_, G_, D_, 0);

    for (int t = 0; t < BAR_; t++) {
        // gates = x0_proj + h0 @ W_hh0^T + b_hh0
        sgemm_nt<<<dim3(G_ / 128, B_ / 128), 256>>>(
            h0, W_hh0, nullptr, nullptr, x0, b_hh0, nullptr,
            gates, B_, G_, D_, 0);
        lstm_cell<<<(B_ * D_) / 256, 256>>>(gates, c0, h0);

        // gates = h0 @ W_ih1^T + b_ih1 + h1_prev @ W_hh1^T + b_hh1  (fused K=2048)
        const float* h1p = (t == 0) ? h1i : (hist + (size_t)(t - 1) * B_ * D_);
        sgemm_nt<<<dim3(G_ / 128, B_ / 128), 256>>>(
            h0, W_ih1, h1p, W_hh1, nullptr, b_ih1, b_hh1,
            gates, B_, G_, D_, 0);
        lstm_cell<<<(B_ * D_) / 256, 256>>>(gates, c1, hist + (size_t)t * B_ * D_);
    }

    // out[b][t][:] = hist[t][b][:] @ W_lin^T + b_lin  (permuted store)
    sgemm_nt<<<dim3(D_ / 128, (BAR_ * B_) / 128), 256>>>(
        hist, W_lin, nullptr, nullptr, nullptr, b_lin, nullptr,
        out, BAR_ * B_, D_, D_, 1);
}

// round 4
// speedup vs baseline: 1.3762x; 1.3762x over previous
#include <cuda_runtime.h>
#include <cstdint>

#define B_   1024
#define D_   1024
#define G_   4096
#define BAR_ 32
#define EPS_ 1e-5f

// GEMM tiling
#define TM 128
#define TN 128
#define BK 32
#define PAD 36                      // floats per smem row (32 + 4 pad)
#define ARR_F (128 * PAD)           // floats per tile array (4608)
#define STG_F (4 * ARR_F)           // floats per stage (18432)
#define SMEM_BYTES (2 * STG_F * 4)  // 147456

// ---------------- device scratch ----------------
__device__ float g_sum[D_], g_sumsq[D_];
__device__ float g_znhi[B_*D_], g_znlo[B_*D_];
__device__ float g_x0[B_*G_];
__device__ float g_gates[B_*G_];
__device__ float g_h0hi[B_*D_], g_h0lo[B_*D_];
__device__ float g_c0[B_*D_], g_c1[B_*D_];
__device__ float g_histhi[(size_t)BAR_*B_*D_], g_histlo[(size_t)BAR_*B_*D_];
__device__ float g_wih0h[G_*D_], g_wih0l[G_*D_];
__device__ float g_whh0h[G_*D_], g_whh0l[G_*D_];
__device__ float g_wih1h[G_*D_], g_wih1l[G_*D_];
__device__ float g_whh1h[G_*D_], g_whh1l[G_*D_];
__device__ float g_wlinh[D_*D_], g_wlinl[D_*D_];

// ---------------- helpers ----------------
__device__ __forceinline__ uint32_t s2u(const void* p){
    uint32_t a;
    asm("{ .reg .u64 t; cvta.to.shared.u64 t, %1; cvt.u32.u64 %0, t; }" : "=r"(a) : "l"(p));
    return a;
}
__device__ __forceinline__ float tf32r(float x){
    float y; asm("cvt.rna.tf32.f32 %0, %1;" : "=f"(y) : "f"(x)); return y;
}
__device__ __forceinline__ float sigf(float x){ return 1.f/(1.f+__expf(-x)); }

__device__ __forceinline__ void cp16(uint32_t dst, const float* src){
    asm volatile("cp.async.cg.shared.global [%0], [%1], 16;"
                 :: "r"(dst), "l"(__cvta_generic_to_global(src)));
}
#define CP_COMMIT() asm volatile("cp.async.commit_group;" ::: "memory")

__device__ __forceinline__ void mma8(float* c, const uint32_t* a, const uint32_t* b){
    asm volatile(
        "mma.sync.aligned.m16n8k8.row.col.f32.tf32.tf32.f32 "
        "{%0,%1,%2,%3}, {%4,%5,%6,%7}, {%8,%9}, {%0,%1,%2,%3};"
        : "+f"(c[0]), "+f"(c[1]), "+f"(c[2]), "+f"(c[3])
        : "r"(a[0]), "r"(a[1]), "r"(a[2]), "r"(a[3]), "r"(b[0]), "r"(b[1]));
}

// ---------------- BatchNorm ----------------
__global__ void bn_reduce(const float* __restrict__ z){
    int c = blockIdx.x, tid = threadIdx.x;
    float s = 0.f, s2 = 0.f;
    for (int r = tid; r < B_; r += 256){
        float v = z[(size_t)r*D_ + c]; s += v; s2 += v*v;
    }
    __shared__ float sh[256], sh2[256];
    sh[tid]=s; sh2[tid]=s2; __syncthreads();
    for (int o=128;o>0;o>>=1){
        if (tid<o){ sh[tid]+=sh[tid+o]; sh2[tid]+=sh2[tid+o]; }
        __syncthreads();
    }
    if (tid==0){ g_sum[c]=sh[0]; g_sumsq[c]=sh2[0]; }
}

__global__ void bn_apply(const float* __restrict__ z, const float* __restrict__ gamma,
                         const float* __restrict__ beta){
    int idx = blockIdx.x*256 + threadIdx.x;
    int d = idx & (D_-1);
    float mean = g_sum[d]*(1.f/B_);
    float var  = g_sumsq[d]*(1.f/B_) - mean*mean;
    float v = (z[idx]-mean)*rsqrtf(var+EPS_)*gamma[d] + beta[d];
    float h = tf32r(v), l = tf32r(v-h);
    g_znhi[idx]=h; g_znlo[idx]=l;
    g_h0hi[idx]=h; g_h0lo[idx]=l;
    g_c0[idx]=v;   g_c1[idx]=v;
}

// ---------------- tf32 hi/lo split ----------------
__global__ void split_k(const float* __restrict__ x, float* __restrict__ hi,
                        float* __restrict__ lo, int n){
    int i = blockIdx.x*256 + threadIdx.x;
    if (i < n){ float v = x[i]; float h = tf32r(v); hi[i]=h; lo[i]=tf32r(v-h); }
}

// ---------------- LSTM cell ----------------
__global__ void lstm_cell(const float* __restrict__ gates, float* __restrict__ c,
                          float* __restrict__ hhi, float* __restrict__ hlo){
    int idx = blockIdx.x*256 + threadIdx.x;
    int b = idx >> 10, d = idx & 1023;
    const float* gr = gates + (size_t)b*G_;
    float gi = gr[d], gf = gr[D_+d], gg = gr[2*D_+d], go = gr[3*D_+d];
    float cn = sigf(gf)*c[idx] + sigf(gi)*tanhf(gg);
    c[idx] = cn;
    float hv = sigf(go)*tanhf(cn);
    float h = tf32r(hv);
    hhi[idx] = h; hlo[idx] = tf32r(hv - h);
}

// ---------------- 3xTF32 mma.sync GEMM (NT, K-fused) ----------------
// C[M,N] = [Cin] + bias1 [+ bias2] + sum_seg A_seg * B_seg^T, 3xTF32 split.
// A: MxK row-major (hi,lo), B: NxK row-major (hi,lo).
__global__ void __launch_bounds__(256,1) gemm3t(
    const float* __restrict__ Ah1, const float* __restrict__ Al1,
    const float* __restrict__ Bh1, const float* __restrict__ Bl1,
    const float* __restrict__ Ah2, const float* __restrict__ Al2,
    const float* __restrict__ Bh2, const float* __restrict__ Bl2,
    const float* __restrict__ Cin, const float* __restrict__ bias1,
    const float* __restrict__ bias2,
    float* __restrict__ C, int M, int N, int K, int nseg, int permute)
{
    extern __shared__ float smf[];
    const int tid  = threadIdx.x;
    const int wid  = tid >> 5, lane = tid & 31;
    const int g    = lane >> 2, t = lane & 3;
    const int wM   = wid & 1;        // 0..1 -> 64-row slice
    const int wN   = wid >> 1;       // 0..3 -> 32-col slice
    const int m0   = blockIdx.y * TM;
    const int n0   = blockIdx.x * TN;

    const int S1 = K / BK;
    const int S  = S1 * nseg;

    float acc[4][4][4];
    #pragma unroll
    for (int i=0;i<4;i++) for (int j=0;j<4;j++) for (int q=0;q<4;q++) acc[i][j][q]=0.f;

    auto load_stage = [&](int s){
        const float *Ah, *Al, *Bh, *Bl; int k0;
        if (s >= S1){ Ah=Ah2; Al=Al2; Bh=Bh2; Bl=Bl2; k0 = (s-S1)*BK; }
        else        { Ah=Ah1; Al=Al1; Bh=Bh1; Bl=Bl1; k0 = s*BK; }
        float* st = smf + (s & 1) * STG_F;
        #pragma unroll
        for (int j = 0; j < 4; j++){
            int e   = tid + j*256;          // 0..1023
            int row = e >> 3, q = (e & 7) << 2;
            uint32_t doff = (uint32_t)((row*PAD + q) * 4);
            size_t  asrc = (size_t)(m0+row)*K + k0 + q;
            size_t  bsrc = (size_t)(n0+row)*K + k0 + q;
            cp16(s2u(st)             + doff, Ah + asrc);
            cp16(s2u(st + ARR_F)     + doff, Al + asrc);
            cp16(s2u(st + 2*ARR_F)   + doff, Bh + bsrc);
            cp16(s2u(st + 3*ARR_F)   + doff, Bl + bsrc);
        }
        CP_COMMIT();
    };

    load_stage(0);
    if (S > 1) load_stage(1);

    for (int s = 0; s < S; s++){
        if (s < S-1) asm volatile("cp.async.wait_group 1;" ::: "memory");
        else         asm volatile("cp.async.wait_group 0;" ::: "memory");
        __syncthreads();

        const float* st = smf + (s & 1) * STG_F;
        const float* pAh = st;
        const float* pAl = st + ARR_F;
        const float* pBh = st + 2*ARR_F;
        const float* pBl = st + 3*ARR_F;

        #pragma unroll
        for (int ks = 0; ks < 4; ks++){
            const int kc = ks * 8;
            uint32_t ah[4][4], al[4][4], bh[4][2], bl[4][2];
            #pragma unroll
            for (int mb = 0; mb < 4; mb++){
                int r0 = (wM*64 + mb*16 + g) * PAD + kc + t;
                ah[mb][0] = __float_as_uint(pAh[r0]);
                ah[mb][1] = __float_as_uint(pAh[r0 + 8*PAD]);
                ah[mb][2] = __float_as_uint(pAh[r0 + 4]);
                ah[mb][3] = __float_as_uint(pAh[r0 + 8*PAD + 4]);
                al[mb][0] = __float_as_uint(pAl[r0]);
                al[mb][1] = __float_as_uint(pAl[r0 + 8*PAD]);
                al[mb][2] = __float_as_uint(pAl[r0 + 4]);
                al[mb][3] = __float_as_uint(pAl[r0 + 8*PAD + 4]);
            }
            #pragma unroll
            for (int nb = 0; nb < 4; nb++){
                int c0 = (wN*32 + nb*8 + g) * PAD + kc + t;
                bh[nb][0] = __float_as_uint(pBh[c0]);
                bh[nb][1] = __float_as_uint(pBh[c0 + 4]);
                bl[nb][0] = __float_as_uint(pBl[c0]);
                bl[nb][1] = __float_as_uint(pBl[c0 + 4]);
            }
            #pragma unroll
            for (int mb = 0; mb < 4; mb++)
                #pragma unroll
                for (int nb = 0; nb < 4; nb++){
                    mma8(acc[mb][nb], ah[mb], bh[nb]);
                    mma8(acc[mb][nb], ah[mb], bl[nb]);
                    mma8(acc[mb][nb], al[mb], bh[nb]);
                }
        }
        __syncthreads();
        if (s + 2 < S) load_stage(s + 2);
    }

    // ---- epilogue ----
    #pragma unroll
    for (int mb = 0; mb < 4; mb++){
        #pragma unroll
        for (int half = 0; half < 2; half++){
            int m = m0 + wM*64 + mb*16 + g + half*8;
            size_t rowoff;
            if (permute){ int tt = m >> 10, bb = m & 1023; rowoff = ((size_t)bb*BAR_ + tt)*(size_t)N; }
            else        { rowoff = (size_t)m*(size_t)N; }
            #pragma unroll
            for (int nb = 0; nb < 4; nb++){
                int n = n0 + wN*32 + nb*8 + 2*t;
                float v0 = acc[mb][nb][half*2 + 0];
                float v1 = acc[mb][nb][half*2 + 1];
                if (bias1){ v0 += bias1[n]; v1 += bias1[n+1]; }
                if (bias2){ v0 += bias2[n]; v1 += bias2[n+1]; }
                if (Cin){
                    float2 cv = *(const float2*)(Cin + (size_t)m*(size_t)N + n);
                    v0 += cv.x; v1 += cv.y;
                }
                float2 o; o.x = v0; o.y = v1;
                *(float2*)(C + rowoff + n) = o;
            }
        }
    }
}

// ---------------- launcher ----------------
extern "C" void kernel_launch(void* const* d_in, const int* in_sizes, int n_in,
                              void* d_out, int out_size)
{
    const float* z     = (const float*)d_in[0];
    const float* gamma = (const float*)d_in[1];
    const float* beta  = (const float*)d_in[2];
    const float* W_ih0 = (const float*)d_in[3];
    const float* W_hh0 = (const float*)d_in[4];
    const float* b_ih0 = (const float*)d_in[5];
    const float* b_hh0 = (const float*)d_in[6];
    const float* W_ih1 = (const float*)d_in[7];
    const float* W_hh1 = (const float*)d_in[8];
    const float* b_ih1 = (const float*)d_in[9];
    const float* b_hh1 = (const float*)d_in[10];
    const float* W_lin = (const float*)d_in[11];
    const float* b_lin = (const float*)d_in[12];
    float* out = (float*)d_out;

    static int attr_set = 0;
    cudaFuncSetAttribute(gemm3t, cudaFuncAttributeMaxDynamicSharedMemorySize, SMEM_BYTES);
    (void)attr_set;

    float *znh,*znl,*x0,*gates,*h0h,*h0l,*c0,*c1,*hh,*hl;
    float *wih0h,*wih0l,*whh0h,*whh0l,*wih1h,*wih1l,*whh1h,*whh1l,*wlinh,*wlinl;
    cudaGetSymbolAddress((void**)&znh, g_znhi);   cudaGetSymbolAddress((void**)&znl, g_znlo);
    cudaGetSymbolAddress((void**)&x0,  g_x0);     cudaGetSymbolAddress((void**)&gates, g_gates);
    cudaGetSymbolAddress((void**)&h0h, g_h0hi);   cudaGetSymbolAddress((void**)&h0l, g_h0lo);
    cudaGetSymbolAddress((void**)&c0,  g_c0);     cudaGetSymbolAddress((void**)&c1,  g_c1);
    cudaGetSymbolAddress((void**)&hh,  g_histhi); cudaGetSymbolAddress((void**)&hl,  g_histlo);
    cudaGetSymbolAddress((void**)&wih0h, g_wih0h); cudaGetSymbolAddress((void**)&wih0l, g_wih0l);
    cudaGetSymbolAddress((void**)&whh0h, g_whh0h); cudaGetSymbolAddress((void**)&whh0l, g_whh0l);
    cudaGetSymbolAddress((void**)&wih1h, g_wih1h); cudaGetSymbolAddress((void**)&wih1l, g_wih1l);
    cudaGetSymbolAddress((void**)&whh1h, g_whh1h); cudaGetSymbolAddress((void**)&whh1l, g_whh1l);
    cudaGetSymbolAddress((void**)&wlinh, g_wlinh); cudaGetSymbolAddress((void**)&wlinl, g_wlinl);

    const int GD = G_*D_, DD = D_*D_;
    split_k<<<GD/256, 256>>>(W_ih0, wih0h, wih0l, GD);
    split_k<<<GD/256, 256>>>(W_hh0, whh0h, whh0l, GD);
    split_k<<<GD/256, 256>>>(W_ih1, wih1h, wih1l, GD);
    split_k<<<GD/256, 256>>>(W_hh1, whh1h, whh1l, GD);
    split_k<<<DD/256, 256>>>(W_lin, wlinh, wlinl, DD);

    bn_reduce<<<D_, 256>>>(z);
    bn_apply<<<(B_*D_)/256, 256>>>(z, gamma, beta);

    // x0_proj = zn @ W_ih0^T + b_ih0
    gemm3t<<<dim3(G_/TN, B_/TM), 256, SMEM_BYTES>>>(
        znh, znl, wih0h, wih0l, nullptr, nullptr, nullptr, nullptr,
        nullptr, b_ih0, nullptr, x0, B_, G_, D_, 1, 0);

    const size_t BD = (size_t)B_*D_;
    for (int t = 0; t < BAR_; t++){
        // gates = x0 + h0 @ W_hh0^T + b_hh0
        gemm3t<<<dim3(G_/TN, B_/TM), 256, SMEM_BYTES>>>(
            h0h, h0l, whh0h, whh0l, nullptr, nullptr, nullptr, nullptr,
            x0, b_hh0, nullptr, gates, B_, G_, D_, 1, 0);
        lstm_cell<<<(B_*D_)/256, 256>>>(gates, c0, h0h, h0l);

        // gates = h0 @ W_ih1^T + h1prev @ W_hh1^T + b_ih1 + b_hh1 (fused K)
        const float* h1ph = (t == 0) ? znh : (hh + (size_t)(t-1)*BD);
        const float* h1pl = (t == 0) ? znl : (hl + (size_t)(t-1)*BD);
        gemm3t<<<dim3(G_/TN, B_/TM), 256, SMEM_BYTES>>>(
            h0h, h0l, wih1h, wih1l, h1ph, h1pl, whh1h, whh1l,
            nullptr, b_ih1, b_hh1, gates, B_, G_, D_, 2, 0);
        lstm_cell<<<(B_*D_)/256, 256>>>(gates, c1, hh + (size_t)t*BD, hl + (size_t)t*BD);
    }

    // out[b][t][:] = hist[t][b][:] @ W_lin^T + b_lin  (permuted store)
    gemm3t<<<dim3(D_/TN, (BAR_*B_)/TM), 256, SMEM_BYTES>>>(
        hh, hl, wlinh, wlinl, nullptr, nullptr, nullptr, nullptr,
        nullptr, b_lin, nullptr, out, BAR_*B_, D_, D_, 1, 1);
}

// round 6
// speedup vs baseline: 1.5038x; 1.0927x over previous
#include <cuda_runtime.h>
#include <cstdint>

#define B_   1024
#define D_   1024
#define G_   4096
#define BAR_ 32
#define EPS_ 1e-5f

// GEMM tiling: CTA 128x256, BK=32, 512 threads (16 warps, each 64x32)
#define TM 128
#define TN 256
#define BK 32
#define NSTAGE 3
#define A_F   (TM*BK)            // 4096 floats
#define STG_F ((TM+TN)*BK)       // 12288 floats (48KB)
#define SMEM_BYTES (NSTAGE*STG_F*4)   // 147456

// ---------------- device scratch ----------------
__device__ float g_sum[D_], g_sumsq[D_];
__device__ float g_zn[B_*D_];
__device__ float g_x0[B_*G_];
__device__ float g_gates[B_*G_];
__device__ float g_h0[B_*D_];
__device__ float g_c0[B_*D_], g_c1[B_*D_];
__device__ float g_hist[(size_t)BAR_*B_*D_];

// ---------------- helpers ----------------
__device__ __forceinline__ uint32_t s2u(const void* p){
    uint32_t a;
    asm("{ .reg .u64 t; cvta.to.shared.u64 t, %1; cvt.u32.u64 %0, t; }" : "=r"(a) : "l"(p));
    return a;
}
__device__ __forceinline__ float tf32r(float x){
    float y; asm("cvt.rna.tf32.f32 %0, %1;" : "=f"(y) : "f"(x)); return y;
}
__device__ __forceinline__ float sigf(float x){ return 1.f/(1.f+__expf(-x)); }

__device__ __forceinline__ void cp16(uint32_t dst, const float* src){
    asm volatile("cp.async.cg.shared.global [%0], [%1], 16;"
                 :: "r"(dst), "l"(__cvta_generic_to_global(src)));
}
#define CP_COMMIT() asm volatile("cp.async.commit_group;" ::: "memory")

__device__ __forceinline__ void mma8(float* c, const uint32_t* a, const uint32_t* b){
    asm volatile(
        "mma.sync.aligned.m16n8k8.row.col.f32.tf32.tf32.f32 "
        "{%0,%1,%2,%3}, {%4,%5,%6,%7}, {%8,%9}, {%0,%1,%2,%3};"
        : "+f"(c[0]), "+f"(c[1]), "+f"(c[2]), "+f"(c[3])
        : "r"(a[0]), "r"(a[1]), "r"(a[2]), "r"(a[3]), "r"(b[0]), "r"(b[1]));
}
__device__ __forceinline__ void ldsm4(uint32_t& r0, uint32_t& r1, uint32_t& r2,
                                      uint32_t& r3, uint32_t addr){
    asm volatile("ldmatrix.sync.aligned.m8n8.x4.shared.b16 {%0,%1,%2,%3}, [%4];"
                 : "=r"(r0), "=r"(r1), "=r"(r2), "=r"(r3) : "r"(addr));
}
__device__ __forceinline__ void split2(uint32_t u, uint32_t& hi, uint32_t& lo){
    float x = __uint_as_float(u);
    float h = tf32r(x);
    hi = __float_as_uint(h);
    lo = __float_as_uint(tf32r(x - h));
}

// ---------------- BatchNorm ----------------
__global__ void bn_reduce(const float* __restrict__ z){
    int c = blockIdx.x, tid = threadIdx.x;
    float s = 0.f, s2 = 0.f;
    for (int r = tid; r < B_; r += 256){
        float v = z[(size_t)r*D_ + c]; s += v; s2 += v*v;
    }
    __shared__ float sh[256], sh2[256];
    sh[tid]=s; sh2[tid]=s2; __syncthreads();
    for (int o=128;o>0;o>>=1){
        if (tid<o){ sh[tid]+=sh[tid+o]; sh2[tid]+=sh2[tid+o]; }
        __syncthreads();
    }
    if (tid==0){ g_sum[c]=sh[0]; g_sumsq[c]=sh2[0]; }
}

__global__ void bn_apply(const float* __restrict__ z, const float* __restrict__ gamma,
                         const float* __restrict__ beta){
    int idx = blockIdx.x*256 + threadIdx.x;
    int d = idx & (D_-1);
    float mean = g_sum[d]*(1.f/B_);
    float var  = g_sumsq[d]*(1.f/B_) - mean*mean;
    float v = (z[idx]-mean)*rsqrtf(var+EPS_)*gamma[d] + beta[d];
    g_zn[idx]=v; g_h0[idx]=v; g_c0[idx]=v; g_c1[idx]=v;
}

// ---------------- LSTM cell ----------------
__global__ void lstm_cell(const float* __restrict__ gates, float* __restrict__ c,
                          float* __restrict__ hout){
    int idx = blockIdx.x*256 + threadIdx.x;
    int b = idx >> 10, d = idx & 1023;
    const float* gr = gates + (size_t)b*G_;
    float gi = gr[d], gf = gr[D_+d], gg = gr[2*D_+d], go = gr[3*D_+d];
    float cn = sigf(gf)*c[idx] + sigf(gi)*tanhf(gg);
    c[idx] = cn;
    hout[idx] = sigf(go)*tanhf(cn);
}

// ---------------- 3xTF32 mma.sync GEMM, fp32 in smem, split in regs ----------------
// C[M,N] = [Cin] + bias1 [+ bias2] + sum_seg A_seg * B_seg^T  (3xTF32)
__global__ void __launch_bounds__(512,1) gemm3t(
    const float* __restrict__ A1, const float* __restrict__ B1,
    const float* __restrict__ A2, const float* __restrict__ B2,
    const float* __restrict__ Cin, const float* __restrict__ bias1,
    const float* __restrict__ bias2,
    float* __restrict__ C, int N, int K, int nseg, int permute)
{
    extern __shared__ float smf[];
    const int tid  = threadIdx.x;
    const int wid  = tid >> 5, lane = tid & 31;
    const int g    = lane >> 2, t = lane & 3;
    const int sub  = lane >> 3, rl = lane & 7;
    const int wM   = wid & 1;          // 0..1 -> 64-row slice
    const int wN   = wid >> 1;         // 0..7 -> 32-col slice
    const int m0   = blockIdx.y * TM;
    const int n0   = blockIdx.x * TN;

    const int S1 = K / BK;
    const int S  = S1 * nseg;

    float acc[4][4][4];
    #pragma unroll
    for (int i=0;i<4;i++) for (int j=0;j<4;j++) for (int q=0;q<4;q++) acc[i][j][q]=0.f;

    auto load_stage = [&](int s){
        const float *A = A1, *Bm = B1; int k0;
        if (s >= S1){ A = A2; Bm = B2; k0 = (s - S1)*BK; } else k0 = s*BK;
        uint32_t sa = s2u(smf + (s % NSTAGE) * STG_F);
        uint32_t sb = sa + A_F*4;
        #pragma unroll
        for (int j = 0; j < 2; j++){
            int e = tid + j*512;                    // 0..1023
            int row = e >> 3, q = e & 7;
            uint32_t d = sa + (((row<<5) + ((q ^ (row&7))<<2)) << 2);
            cp16(d, A + (size_t)(m0+row)*K + k0 + (q<<2));
        }
        #pragma unroll
        for (int j = 0; j < 4; j++){
            int e = tid + j*512;                    // 0..2047
            int row = e >> 3, q = e & 7;
            uint32_t d = sb + (((row<<5) + ((q ^ (row&7))<<2)) << 2);
            cp16(d, Bm + (size_t)(n0+row)*K + k0 + (q<<2));
        }
        CP_COMMIT();
    };

    load_stage(0); load_stage(1); load_stage(2);

    for (int s = 0; s < S; s++){
        if (s < S-2)      asm volatile("cp.async.wait_group 2;" ::: "memory");
        else if (s == S-2) asm volatile("cp.async.wait_group 1;" ::: "memory");
        else              asm volatile("cp.async.wait_group 0;" ::: "memory");
        __syncthreads();

        uint32_t sa = s2u(smf + (s % NSTAGE) * STG_F);
        uint32_t sb = sa + A_F*4;

        #pragma unroll
        for (int ks = 0; ks < 4; ks++){
            const int g4 = ks << 1;                 // k granule base (16B units)
            uint32_t ah[4][4], al[4][4];
            #pragma unroll
            for (int mb = 0; mb < 4; mb++){
                int row  = wM*64 + mb*16 + ((sub&1)<<3) + rl;
                int gran = g4 + (sub>>1);
                uint32_t addr = sa + (((row<<5) + ((gran ^ (row&7))<<2)) << 2);
                uint32_t u0,u1,u2,u3; ldsm4(u0,u1,u2,u3,addr);
                split2(u0, ah[mb][0], al[mb][0]);
                split2(u1, ah[mb][1], al[mb][1]);
                split2(u2, ah[mb][2], al[mb][2]);
                split2(u3, ah[mb][3], al[mb][3]);
            }
            #pragma unroll
            for (int nbp = 0; nbp < 2; nbp++){
                int row  = wN*32 + nbp*16 + ((sub>>1)<<3) + rl;
                int gran = g4 + (sub&1);
                uint32_t addr = sb + (((row<<5) + ((gran ^ (row&7))<<2)) << 2);
                uint32_t u0,u1,u2,u3; ldsm4(u0,u1,u2,u3,addr);
                uint32_t bh[2][2], bl[2][2];
                split2(u0, bh[0][0], bl[0][0]);
                split2(u1, bh[0][1], bl[0][1]);
                split2(u2, bh[1][0], bl[1][0]);
                split2(u3, bh[1][1], bl[1][1]);
                #pragma unroll
                for (int mb = 0; mb < 4; mb++)
                    #pragma unroll
                    for (int j = 0; j < 2; j++){
                        float* a = acc[mb][nbp*2 + j];
                        mma8(a, ah[mb], bh[j]);
                        mma8(a, ah[mb], bl[j]);
                        mma8(a, al[mb], bh[j]);
                    }
            }
        }
        __syncthreads();
        if (s + NSTAGE < S) load_stage(s + NSTAGE);
    }

    // ---- epilogue ----
    #pragma unroll
    for (int mb = 0; mb < 4; mb++){
        #pragma unroll
        for (int half = 0; half < 2; half++){
            int m = m0 + wM*64 + mb*16 + g + half*8;
            size_t rowoff;
            if (permute){ int tt = m >> 10, bb = m & 1023; rowoff = ((size_t)bb*BAR_ + tt)*(size_t)N; }
            else        { rowoff = (size_t)m*(size_t)N; }
            #pragma unroll
            for (int nb = 0; nb < 4; nb++){
                int n = n0 + wN*32 + nb*8 + 2*t;
                float v0 = acc[mb][nb][half*2 + 0];
                float v1 = acc[mb][nb][half*2 + 1];
                if (bias1){ v0 += bias1[n]; v1 += bias1[n+1]; }
                if (bias2){ v0 += bias2[n]; v1 += bias2[n+1]; }
                if (Cin){
                    float2 cv = *(const float2*)(Cin + (size_t)m*(size_t)N + n);
                    v0 += cv.x; v1 += cv.y;
                }
                float2 o; o.x = v0; o.y = v1;
                *(float2*)(C + rowoff + n) = o;
            }
        }
    }
}

// ---------------- launcher ----------------
extern "C" void kernel_launch(void* const* d_in, const int* in_sizes, int n_in,
                              void* d_out, int out_size)
{
    const float* z     = (const float*)d_in[0];
    const float* gamma = (const float*)d_in[1];
    const float* beta  = (const float*)d_in[2];
    const float* W_ih0 = (const float*)d_in[3];
    const float* W_hh0 = (const float*)d_in[4];
    const float* b_ih0 = (const float*)d_in[5];
    const float* b_hh0 = (const float*)d_in[6];
    const float* W_ih1 = (const float*)d_in[7];
    const float* W_hh1 = (const float*)d_in[8];
    const float* b_ih1 = (const float*)d_in[9];
    const float* b_hh1 = (const float*)d_in[10];
    const float* W_lin = (const float*)d_in[11];
    const float* b_lin = (const float*)d_in[12];
    float* out = (float*)d_out;

    cudaFuncSetAttribute(gemm3t, cudaFuncAttributeMaxDynamicSharedMemorySize, SMEM_BYTES);

    float *zn,*x0,*gates,*h0,*c0,*c1,*hist;
    cudaGetSymbolAddress((void**)&zn,    g_zn);
    cudaGetSymbolAddress((void**)&x0,    g_x0);
    cudaGetSymbolAddress((void**)&gates, g_gates);
    cudaGetSymbolAddress((void**)&h0,    g_h0);
    cudaGetSymbolAddress((void**)&c0,    g_c0);
    cudaGetSymbolAddress((void**)&c1,    g_c1);
    cudaGetSymbolAddress((void**)&hist,  g_hist);

    bn_reduce<<<D_, 256>>>(z);
    bn_apply<<<(B_*D_)/256, 256>>>(z, gamma, beta);

    // x0_proj = zn @ W_ih0^T + b_ih0
    gemm3t<<<dim3(G_/TN, B_/TM), 512, SMEM_BYTES>>>(
        zn, W_ih0, nullptr, nullptr, nullptr, b_ih0, nullptr,
        x0, G_, D_, 1, 0);

    const size_t BD = (size_t)B_*D_;
    for (int t = 0; t < BAR_; t++){
        // gates = x0 + h0 @ W_hh0^T + b_hh0
        gemm3t<<<dim3(G_/TN, B_/TM), 512, SMEM_BYTES>>>(
            h0, W_hh0, nullptr, nullptr, x0, b_hh0, nullptr,
            gates, G_, D_, 1, 0);
        lstm_cell<<<(B_*D_)/256, 256>>>(gates, c0, h0);

        // gates = h0 @ W_ih1^T + h1prev @ W_hh1^T + b_ih1 + b_hh1 (fused K)
        const float* h1p = (t == 0) ? zn : (hist + (size_t)(t-1)*BD);
        gemm3t<<<dim3(G_/TN, B_/TM), 512, SMEM_BYTES>>>(
            h0, W_ih1, h1p, W_hh1, nullptr, b_ih1, b_hh1,
            gates, G_, D_, 2, 0);
        lstm_cell<<<(B_*D_)/256, 256>>>(gates, c1, hist + (size_t)t*BD);
    }

    // out[b][t][:] = hist[t][b][:] @ W_lin^T + b_lin  (permuted store)
    gemm3t<<<dim3(D_/TN, (BAR_*B_)/TM), 512, SMEM_BYTES>>>(
        hist, W_lin, nullptr, nullptr, nullptr, b_lin, nullptr,
        out, D_, D_, 1, 1);
}

// round 7
// speedup vs baseline: 2.5445x; 1.6921x over previous
#include <cuda_runtime.h>
#include <cuda_fp16.h>
#include <cstdint>

#define B_   1024
#define D_   1024
#define G_   4096
#define BAR_ 32
#define EPS_ 1e-5f

// GEMM tiling: CTA 128x256, BK=32, 512 threads (16 warps, each 64x32)
#define TM 128
#define TN 256
#define BK 32
#define NSTAGE 3
#define A_BYTES  (TM*BK*2)               // 8192 per array
#define B_BYTES  (TN*BK*2)               // 16384 per array
#define STG_BYTES (2*A_BYTES + 2*B_BYTES) // 49152
#define SMEM_BYTES (NSTAGE*STG_BYTES)     // 147456

// ---------------- device scratch ----------------
__device__ float g_sum[D_], g_sumsq[D_];
__device__ float g_x0[B_*G_];
__device__ float g_gates[B_*G_];
__device__ float g_c0[B_*D_], g_c1[B_*D_];
__device__ __align__(128) __half g_znh[B_*D_],  g_znl[B_*D_];
__device__ __align__(128) __half g_h0h[B_*D_],  g_h0l[B_*D_];
__device__ __align__(128) __half g_histh[(size_t)BAR_*B_*D_], g_histl[(size_t)BAR_*B_*D_];
__device__ __align__(128) __half g_wih0h[G_*D_], g_wih0l[G_*D_];
__device__ __align__(128) __half g_whh0h[G_*D_], g_whh0l[G_*D_];
__device__ __align__(128) __half g_wih1h[G_*D_], g_wih1l[G_*D_];
__device__ __align__(128) __half g_whh1h[G_*D_], g_whh1l[G_*D_];
__device__ __align__(128) __half g_wlinh[D_*D_], g_wlinl[D_*D_];

// ---------------- helpers ----------------
__device__ __forceinline__ uint32_t s2u(const void* p){
    uint32_t a;
    asm("{ .reg .u64 t; cvta.to.shared.u64 t, %1; cvt.u32.u64 %0, t; }" : "=r"(a) : "l"(p));
    return a;
}
__device__ __forceinline__ float sigf(float x){ return 1.f/(1.f+__expf(-x)); }

__device__ __forceinline__ void hsplit(float x, __half& hi, __half& lo){
    __half h = __float2half_rn(x);
    hi = h;
    lo = __float2half_rn(x - __half2float(h));
}

__device__ __forceinline__ void cp16(uint32_t dst, const void* src){
    asm volatile("cp.async.cg.shared.global [%0], [%1], 16;"
                 :: "r"(dst), "l"(__cvta_generic_to_global(src)));
}
#define CP_COMMIT() asm volatile("cp.async.commit_group;" ::: "memory")

__device__ __forceinline__ void mma16(float* c, const uint32_t* a, const uint32_t* b){
    asm volatile(
        "mma.sync.aligned.m16n8k16.row.col.f32.f16.f16.f32 "
        "{%0,%1,%2,%3}, {%4,%5,%6,%7}, {%8,%9}, {%0,%1,%2,%3};"
        : "+f"(c[0]), "+f"(c[1]), "+f"(c[2]), "+f"(c[3])
        : "r"(a[0]), "r"(a[1]), "r"(a[2]), "r"(a[3]), "r"(b[0]), "r"(b[1]));
}
__device__ __forceinline__ void ldsm4(uint32_t& r0, uint32_t& r1, uint32_t& r2,
                                      uint32_t& r3, uint32_t addr){
    asm volatile("ldmatrix.sync.aligned.m8n8.x4.shared.b16 {%0,%1,%2,%3}, [%4];"
                 : "=r"(r0), "=r"(r1), "=r"(r2), "=r"(r3) : "r"(addr));
}

// ---------------- BatchNorm ----------------
__global__ void bn_reduce(const float* __restrict__ z){
    int c = blockIdx.x, tid = threadIdx.x;
    float s = 0.f, s2 = 0.f;
    for (int r = tid; r < B_; r += 256){
        float v = z[(size_t)r*D_ + c]; s += v; s2 += v*v;
    }
    __shared__ float sh[256], sh2[256];
    sh[tid]=s; sh2[tid]=s2; __syncthreads();
    for (int o=128;o>0;o>>=1){
        if (tid<o){ sh[tid]+=sh[tid+o]; sh2[tid]+=sh2[tid+o]; }
        __syncthreads();
    }
    if (tid==0){ g_sum[c]=sh[0]; g_sumsq[c]=sh2[0]; }
}

__global__ void bn_apply(const float* __restrict__ z, const float* __restrict__ gamma,
                         const float* __restrict__ beta){
    int idx = blockIdx.x*256 + threadIdx.x;
    int d = idx & (D_-1);
    float mean = g_sum[d]*(1.f/B_);
    float var  = g_sumsq[d]*(1.f/B_) - mean*mean;
    float v = (z[idx]-mean)*rsqrtf(var+EPS_)*gamma[d] + beta[d];
    __half h, l; hsplit(v, h, l);
    g_znh[idx]=h; g_znl[idx]=l;
    g_h0h[idx]=h; g_h0l[idx]=l;
    g_c0[idx]=v;  g_c1[idx]=v;
}

// ---------------- weight split fp32 -> fp16 hi/lo ----------------
__global__ void split_k(const float* __restrict__ x, __half* __restrict__ hi,
                        __half* __restrict__ lo, int n){
    int i = blockIdx.x*256 + threadIdx.x;
    if (i < n){ __half h, l; hsplit(x[i], h, l); hi[i]=h; lo[i]=l; }
}

// ---------------- LSTM cell ----------------
__global__ void lstm_cell(const float* __restrict__ gates, float* __restrict__ c,
                          __half* __restrict__ hh, __half* __restrict__ hl){
    int idx = blockIdx.x*256 + threadIdx.x;
    int b = idx >> 10, d = idx & 1023;
    const float* gr = gates + (size_t)b*G_;
    float gi = gr[d], gf = gr[D_+d], gg = gr[2*D_+d], go = gr[3*D_+d];
    float cn = sigf(gf)*c[idx] + sigf(gi)*tanhf(gg);
    c[idx] = cn;
    float hv = sigf(go)*tanhf(cn);
    __half h, l; hsplit(hv, h, l);
    hh[idx] = h; hl[idx] = l;
}

// ---------------- 3-term fp16 mma.sync GEMM (NT, K-fused) ----------------
// C = [Cin] + bias1 [+bias2] + sum_seg (Ah+Al)(Bh+Bl)^T  (hh+hl+lh terms)
__global__ void __launch_bounds__(512,1) gemm3h(
    const __half* __restrict__ A1h, const __half* __restrict__ A1l,
    const __half* __restrict__ B1h, const __half* __restrict__ B1l,
    const __half* __restrict__ A2h, const __half* __restrict__ A2l,
    const __half* __restrict__ B2h, const __half* __restrict__ B2l,
    const float* __restrict__ Cin, const float* __restrict__ bias1,
    const float* __restrict__ bias2,
    float* __restrict__ C, int N, int K, int nseg, int permute)
{
    extern __shared__ char smc[];
    const int tid  = threadIdx.x;
    const int wid  = tid >> 5, lane = tid & 31;
    const int g    = lane >> 2, t = lane & 3;
    const int sub  = lane >> 3, rl = lane & 7;
    const int wM   = wid & 1;          // 0..1 -> 64-row slice
    const int wN   = wid >> 1;         // 0..7 -> 32-col slice
    const int m0   = blockIdx.y * TM;
    const int n0   = blockIdx.x * TN;

    const int S1 = K / BK;
    const int S  = S1 * nseg;

    float acc[4][4][4];
    #pragma unroll
    for (int i=0;i<4;i++) for (int j=0;j<4;j++) for (int q=0;q<4;q++) acc[i][j][q]=0.f;

    auto load_stage = [&](int s){
        const __half *Ah = A1h, *Al = A1l, *Bh = B1h, *Bl = B1l; int k0;
        if (s >= S1){ Ah=A2h; Al=A2l; Bh=B2h; Bl=B2l; k0 = (s - S1)*BK; } else k0 = s*BK;
        uint32_t st = s2u(smc + (s % NSTAGE) * STG_BYTES);
        // A arrays: 128 rows x 4 granules(16B) each, 512 xfers per array
        {
            int row = tid >> 2, gran = tid & 3;
            uint32_t doff = (uint32_t)(row*64 + ((gran ^ (row & 3))<<4));
            size_t soff = (size_t)(m0+row)*K + k0 + gran*8;
            cp16(st + doff,            Ah + soff);
            cp16(st + A_BYTES + doff,  Al + soff);
        }
        // B arrays: 256 rows x 4 granules, 1024 xfers per array
        #pragma unroll
        for (int j = 0; j < 2; j++){
            int e = tid + j*512;
            int row = e >> 2, gran = e & 3;
            uint32_t doff = (uint32_t)(row*64 + ((gran ^ (row & 3))<<4));
            size_t soff = (size_t)(n0+row)*K + k0 + gran*8;
            cp16(st + 2*A_BYTES + doff,            Bh + soff);
            cp16(st + 2*A_BYTES + B_BYTES + doff,  Bl + soff);
        }
        CP_COMMIT();
    };

    load_stage(0); load_stage(1); load_stage(2);

    for (int s = 0; s < S; s++){
        if (s < S-2)       asm volatile("cp.async.wait_group 2;" ::: "memory");
        else if (s == S-2) asm volatile("cp.async.wait_group 1;" ::: "memory");
        else               asm volatile("cp.async.wait_group 0;" ::: "memory");
        __syncthreads();

        uint32_t sa = s2u(smc + (s % NSTAGE) * STG_BYTES);
        uint32_t sbB = sa + 2*A_BYTES;

        #pragma unroll
        for (int ks = 0; ks < 2; ks++){              // two k16 slices per stage
            const int gran = 2*ks + (sub >> 1);
            uint32_t ah[4][4], al[4][4];
            #pragma unroll
            for (int mb = 0; mb < 4; mb++){
                int row = wM*64 + mb*16 + ((sub & 1)<<3) + rl;
                uint32_t off = (uint32_t)(row*64 + ((gran ^ (row & 3))<<4));
                ldsm4(ah[mb][0], ah[mb][1], ah[mb][2], ah[mb][3], sa + off);
                ldsm4(al[mb][0], al[mb][1], al[mb][2], al[mb][3], sa + A_BYTES + off);
            }
            #pragma unroll
            for (int np = 0; np < 2; np++){          // each covers 2 n8 blocks
                int row = wN*32 + np*16 + ((sub & 1)<<3) + rl;
                uint32_t off = (uint32_t)(row*64 + ((gran ^ (row & 3))<<4));
                uint32_t h0,h1,h2,h3, l0,l1,l2,l3;
                ldsm4(h0,h1,h2,h3, sbB + off);
                ldsm4(l0,l1,l2,l3, sbB + B_BYTES + off);
                uint32_t bh[2][2] = {{h0,h2},{h1,h3}};
                uint32_t bl[2][2] = {{l0,l2},{l1,l3}};
                #pragma unroll
                for (int mb = 0; mb < 4; mb++)
                    #pragma unroll
                    for (int j = 0; j < 2; j++){
                        float* a = acc[mb][np*2 + j];
                        mma16(a, ah[mb], bh[j]);
                        mma16(a, ah[mb], bl[j]);
                        mma16(a, al[mb], bh[j]);
                    }
            }
        }
        __syncthreads();
        if (s + NSTAGE < S) load_stage(s + NSTAGE);
    }

    // ---- epilogue ----
    #pragma unroll
    for (int mb = 0; mb < 4; mb++){
        #pragma unroll
        for (int half = 0; half < 2; half++){
            int m = m0 + wM*64 + mb*16 + g + half*8;
            size_t rowoff;
            if (permute){ int tt = m >> 10, bb = m & 1023; rowoff = ((size_t)bb*BAR_ + tt)*(size_t)N; }
            else        { rowoff = (size_t)m*(size_t)N; }
            #pragma unroll
            for (int nb = 0; nb < 4; nb++){
                int n = n0 + wN*32 + nb*8 + 2*t;
                float v0 = acc[mb][nb][half*2 + 0];
                float v1 = acc[mb][nb][half*2 + 1];
                if (bias1){ v0 += bias1[n]; v1 += bias1[n+1]; }
                if (bias2){ v0 += bias2[n]; v1 += bias2[n+1]; }
                if (Cin){
                    float2 cv = *(const float2*)(Cin + (size_t)m*(size_t)N + n);
                    v0 += cv.x; v1 += cv.y;
                }
                float2 o; o.x = v0; o.y = v1;
                *(float2*)(C + rowoff + n) = o;
            }
        }
    }
}

// ---------------- launcher ----------------
extern "C" void kernel_launch(void* const* d_in, const int* in_sizes, int n_in,
                              void* d_out, int out_size)
{
    const float* z     = (const float*)d_in[0];
    const float* gamma = (const float*)d_in[1];
    const float* beta  = (const float*)d_in[2];
    const float* W_ih0 = (const float*)d_in[3];
    const float* W_hh0 = (const float*)d_in[4];
    const float* b_ih0 = (const float*)d_in[5];
    const float* b_hh0 = (const float*)d_in[6];
    const float* W_ih1 = (const float*)d_in[7];
    const float* W_hh1 = (const float*)d_in[8];
    const float* b_ih1 = (const float*)d_in[9];
    const float* b_hh1 = (const float*)d_in[10];
    const float* W_lin = (const float*)d_in[11];
    const float* b_lin = (const float*)d_in[12];
    float* out = (float*)d_out;

    cudaFuncSetAttribute(gemm3h, cudaFuncAttributeMaxDynamicSharedMemorySize, SMEM_BYTES);

    float *x0,*gates,*c0,*c1;
    __half *znh,*znl,*h0h,*h0l,*hh,*hl;
    __half *wih0h,*wih0l,*whh0h,*whh0l,*wih1h,*wih1l,*whh1h,*whh1l,*wlinh,*wlinl;
    cudaGetSymbolAddress((void**)&x0,    g_x0);
    cudaGetSymbolAddress((void**)&gates, g_gates);
    cudaGetSymbolAddress((void**)&c0,    g_c0);
    cudaGetSymbolAddress((void**)&c1,    g_c1);
    cudaGetSymbolAddress((void**)&znh,   g_znh);   cudaGetSymbolAddress((void**)&znl, g_znl);
    cudaGetSymbolAddress((void**)&h0h,   g_h0h);   cudaGetSymbolAddress((void**)&h0l, g_h0l);
    cudaGetSymbolAddress((void**)&hh,    g_histh); cudaGetSymbolAddress((void**)&hl,  g_histl);
    cudaGetSymbolAddress((void**)&wih0h, g_wih0h); cudaGetSymbolAddress((void**)&wih0l, g_wih0l);
    cudaGetSymbolAddress((void**)&whh0h, g_whh0h); cudaGetSymbolAddress((void**)&whh0l, g_whh0l);
    cudaGetSymbolAddress((void**)&wih1h, g_wih1h); cudaGetSymbolAddress((void**)&wih1l, g_wih1l);
    cudaGetSymbolAddress((void**)&whh1h, g_whh1h); cudaGetSymbolAddress((void**)&whh1l, g_whh1l);
    cudaGetSymbolAddress((void**)&wlinh, g_wlinh); cudaGetSymbolAddress((void**)&wlinl, g_wlinl);

    const int GD = G_*D_, DD = D_*D_;
    split_k<<<GD/256, 256>>>(W_ih0, wih0h, wih0l, GD);
    split_k<<<GD/256, 256>>>(W_hh0, whh0h, whh0l, GD);
    split_k<<<GD/256, 256>>>(W_ih1, wih1h, wih1l, GD);
    split_k<<<GD/256, 256>>>(W_hh1, whh1h, whh1l, GD);
    split_k<<<DD/256, 256>>>(W_lin, wlinh, wlinl, DD);

    bn_reduce<<<D_, 256>>>(z);
    bn_apply<<<(B_*D_)/256, 256>>>(z, gamma, beta);

    // x0_proj = zn @ W_ih0^T + b_ih0
    gemm3h<<<dim3(G_/TN, B_/TM), 512, SMEM_BYTES>>>(
        znh, znl, wih0h, wih0l, nullptr, nullptr, nullptr, nullptr,
        nullptr, b_ih0, nullptr, x0, G_, D_, 1, 0);

    const size_t BD = (size_t)B_*D_;
    for (int t = 0; t < BAR_; t++){
        // gates = x0 + h0 @ W_hh0^T + b_hh0
        gemm3h<<<dim3(G_/TN, B_/TM), 512, SMEM_BYTES>>>(
            h0h, h0l, whh0h, whh0l, nullptr, nullptr, nullptr, nullptr,
            x0, b_hh0, nullptr, gates, G_, D_, 1, 0);
        lstm_cell<<<(B_*D_)/256, 256>>>(gates, c0, h0h, h0l);

        // gates = h0 @ W_ih1^T + h1prev @ W_hh1^T + b_ih1 + b_hh1 (fused K)
        const __half* h1ph = (t == 0) ? znh : (hh + (size_t)(t-1)*BD);
        const __half* h1pl = (t == 0) ? znl : (hl + (size_t)(t-1)*BD);
        gemm3h<<<dim3(G_/TN, B_/TM), 512, SMEM_BYTES>>>(
            h0h, h0l, wih1h, wih1l, h1ph, h1pl, whh1h, whh1l,
            nullptr, b_ih1, b_hh1, gates, G_, D_, 2, 0);
        lstm_cell<<<(B_*D_)/256, 256>>>(gates, c1, hh + (size_t)t*BD, hl + (size_t)t*BD);
    }

    // out[b][t][:] = hist[t][b][:] @ W_lin^T + b_lin  (permuted store)
    gemm3h<<<dim3(D_/TN, (BAR_*B_)/TM), 512, SMEM_BYTES>>>(
        hh, hl, wlinh, wlinl, nullptr, nullptr, nullptr, nullptr,
        nullptr, b_lin, nullptr, out, D_, D_, 1, 1);
}